// round 3
// baseline (speedup 1.0000x reference)
#include <cuda_runtime.h>

#define NN 100000
#define EE 1600000
#define PP 100000
#define D  128
#define NB 391   // ceil(NN/256)

typedef unsigned long long ull;

// ---------------- f32x2 helpers ----------------
__device__ __forceinline__ ull bc2(float x) {
    ull r;
    asm("mov.b64 %0, {%1, %1};" : "=l"(r) : "f"(x));
    return r;
}
__device__ __forceinline__ ull fma2(ull a, ull b, ull c) {
    ull d;
    asm("fma.rn.f32x2 %0, %1, %2, %3;" : "=l"(d) : "l"(a), "l"(b), "l"(c));
    return d;
}
__device__ __forceinline__ float2 up2(ull v) {
    float2 f;
    asm("mov.b64 {%0, %1}, %2;" : "=f"(f.x), "=f"(f.y) : "l"(v));
    return f;
}

// ---------------- scratch (device globals; no allocation) ----------------
__device__ __align__(128) float g_hA [(size_t)NN * D];
__device__ __align__(128) float g_hB [(size_t)NN * D];
__device__ __align__(128) float g_rep[(size_t)NN * D];
__device__ int   g_cnt_in [NN];
__device__ int   g_cnt_out[NN];
__device__ float g_rs_in  [NN];
__device__ float g_rs_out [NN];
__device__ int   g_row_ptr[NN + 1];
__device__ int   g_cursor [NN];
__device__ int   g_col    [EE];
__device__ int   g_bsum   [NB];
__device__ int   g_boff   [NB];

// ---------------- graph structure ----------------
__global__ void zero_cnt_kernel() {
    int v = blockIdx.x * blockDim.x + threadIdx.x;
    if (v < NN) { g_cnt_in[v] = 0; g_cnt_out[v] = 0; }
}

__global__ void count_deg_kernel(const int* __restrict__ src, const int* __restrict__ dst) {
    int e = blockIdx.x * blockDim.x + threadIdx.x;
    if (e < EE) {
        atomicAdd(&g_cnt_out[src[e]], 1);
        atomicAdd(&g_cnt_in [dst[e]], 1);
    }
}

__global__ void scanA_kernel() {
    __shared__ int sh[256];
    int i = blockIdx.x * 256 + threadIdx.x;
    int v = (i < NN) ? g_cnt_in[i] : 0;
    sh[threadIdx.x] = v;
    __syncthreads();
    for (int off = 128; off > 0; off >>= 1) {
        if (threadIdx.x < off) sh[threadIdx.x] += sh[threadIdx.x + off];
        __syncthreads();
    }
    if (threadIdx.x == 0) g_bsum[blockIdx.x] = sh[0];
}

__global__ void scanB_kernel() {
    __shared__ int sh[512];
    int t = threadIdx.x;
    int v = (t < NB) ? g_bsum[t] : 0;
    sh[t] = v;
    __syncthreads();
    for (int off = 1; off < 512; off <<= 1) {
        int x = (t >= off) ? sh[t - off] : 0;
        __syncthreads();
        sh[t] += x;
        __syncthreads();
    }
    if (t < NB) g_boff[t] = sh[t] - v;
}

__global__ void scanC_kernel() {
    __shared__ int sh[256];
    int b = blockIdx.x;
    int i = b * 256 + threadIdx.x;
    int v = (i < NN) ? g_cnt_in[i] : 0;
    sh[threadIdx.x] = v;
    __syncthreads();
    for (int off = 1; off < 256; off <<= 1) {
        int x = (threadIdx.x >= off) ? sh[threadIdx.x - off] : 0;
        __syncthreads();
        sh[threadIdx.x] += x;
        __syncthreads();
    }
    if (i < NN) {
        int incl = g_boff[b] + sh[threadIdx.x];
        g_row_ptr[i + 1] = incl;
        g_cursor[i] = incl - v;
        int ci = v; if (ci < 1) ci = 1;
        int co = g_cnt_out[i]; if (co < 1) co = 1;
        g_rs_in [i] = rsqrtf((float)ci);
        g_rs_out[i] = rsqrtf((float)co);
        if (i == 0) g_row_ptr[0] = 0;
    }
}

__global__ void scatter_edges_kernel(const int* __restrict__ src, const int* __restrict__ dst) {
    int e = blockIdx.x * blockDim.x + threadIdx.x;
    if (e < EE) {
        int pos = atomicAdd(&g_cursor[dst[e]], 1);
        g_col[pos] = src[e];
    }
}

// ---------------- FFMA2 GEMM inner-step macro ----------------
// acc[i][q]: row i (4 rows), col-pair q (cols c0+2q, c0+2q+1)
#define K_STEP(KQ, A0, A1, A2, A3)                                          \
    {                                                                       \
        const float* wrow = Wsh + (k4 + (KQ)) * 128 + c0;                   \
        ulonglong2 wA = *(const ulonglong2*)(wrow);                         \
        ulonglong2 wB = *(const ulonglong2*)(wrow + 4);                     \
        ull p0 = bc2(A0), p1 = bc2(A1), p2 = bc2(A2), p3 = bc2(A3);         \
        acc[0][0] = fma2(p0, wA.x, acc[0][0]);                              \
        acc[0][1] = fma2(p0, wA.y, acc[0][1]);                              \
        acc[0][2] = fma2(p0, wB.x, acc[0][2]);                              \
        acc[0][3] = fma2(p0, wB.y, acc[0][3]);                              \
        acc[1][0] = fma2(p1, wA.x, acc[1][0]);                              \
        acc[1][1] = fma2(p1, wA.y, acc[1][1]);                              \
        acc[1][2] = fma2(p1, wB.x, acc[1][2]);                              \
        acc[1][3] = fma2(p1, wB.y, acc[1][3]);                              \
        acc[2][0] = fma2(p2, wA.x, acc[2][0]);                              \
        acc[2][1] = fma2(p2, wA.y, acc[2][1]);                              \
        acc[2][2] = fma2(p2, wB.x, acc[2][2]);                              \
        acc[2][3] = fma2(p2, wB.y, acc[2][3]);                              \
        acc[3][0] = fma2(p3, wA.x, acc[3][0]);                              \
        acc[3][1] = fma2(p3, wA.y, acc[3][1]);                              \
        acc[3][2] = fma2(p3, wB.x, acc[3][2]);                              \
        acc[3][3] = fma2(p3, wB.y, acc[3][3]);                              \
    }

#define ZERO_ACC()                                                          \
    _Pragma("unroll")                                                       \
    for (int i = 0; i < 4; i++)                                             \
        _Pragma("unroll")                                                   \
        for (int q = 0; q < 4; q++) acc[i][q] = 0ULL;

#define STAGE_W(WPTR)                                                       \
    _Pragma("unroll")                                                       \
    for (int i = 0; i < 2; i++) {                                           \
        int idx = tid + i * 256;                                            \
        int wr  = idx >> 5;                                                 \
        int wc4 = idx & 31;                                                 \
        *(float4*)&Wsh[wr * 128 + wc4 * 4] =                                \
            *(const float4*)((WPTR) + (size_t)(kk + wr) * 128 + wc4 * 4);   \
    }

// ---------------- fused node MLP ----------------
// hs = (relu(x@W1+b1)@W2+b2)*rs_out ; rep = gamma0*h.  BM=64, 256 threads.
__global__ __launch_bounds__(256) void mlp_kernel(
        const float* __restrict__ x,
        const float* __restrict__ w1, const float* __restrict__ b1,
        const float* __restrict__ w2, const float* __restrict__ b2,
        const float* __restrict__ gam,
        float* __restrict__ hs, float* __restrict__ rep) {
    __shared__ __align__(16) float Ash[64 * 20];
    __shared__ __align__(16) float Wsh[16 * 128];
    __shared__ __align__(16) float Tsh[64 * 132];

    const int tid = threadIdx.x;
    const int c0  = (tid & 15) * 8;   // cols c0..c0+7
    const int r0  = (tid >> 4) * 4;   // rows r0..r0+3 (local)
    const int blockRow = blockIdx.x * 64;

    const int a_row = tid >> 2;
    const int a_c4  = tid & 3;
    const int gm    = blockRow + a_row;
    const bool a_ok = (gm < NN);

    ull acc[4][4];
    ZERO_ACC();

    // ---- GEMM1: relu(x@W1+b1) -> Tsh ----
    for (int kk = 0; kk < D; kk += 16) {
        float4 av = make_float4(0.f, 0.f, 0.f, 0.f);
        if (a_ok) av = *(const float4*)(x + (size_t)gm * D + kk + a_c4 * 4);
        *(float4*)&Ash[a_row * 20 + a_c4 * 4] = av;
        STAGE_W(w1);
        __syncthreads();
#pragma unroll
        for (int k4 = 0; k4 < 16; k4 += 4) {
            float4 a0 = *(const float4*)&Ash[(r0 + 0) * 20 + k4];
            float4 a1 = *(const float4*)&Ash[(r0 + 1) * 20 + k4];
            float4 a2 = *(const float4*)&Ash[(r0 + 2) * 20 + k4];
            float4 a3 = *(const float4*)&Ash[(r0 + 3) * 20 + k4];
            K_STEP(0, a0.x, a1.x, a2.x, a3.x)
            K_STEP(1, a0.y, a1.y, a2.y, a3.y)
            K_STEP(2, a0.z, a1.z, a2.z, a3.z)
            K_STEP(3, a0.w, a1.w, a2.w, a3.w)
        }
        __syncthreads();
    }
    {
        float4 bx = *(const float4*)(b1 + c0);
        float4 by = *(const float4*)(b1 + c0 + 4);
#pragma unroll
        for (int i = 0; i < 4; i++) {
            float2 v0 = up2(acc[i][0]);
            float2 v1 = up2(acc[i][1]);
            float2 v2 = up2(acc[i][2]);
            float2 v3 = up2(acc[i][3]);
            float4 o0, o1;
            o0.x = fmaxf(v0.x + bx.x, 0.f); o0.y = fmaxf(v0.y + bx.y, 0.f);
            o0.z = fmaxf(v1.x + bx.z, 0.f); o0.w = fmaxf(v1.y + bx.w, 0.f);
            o1.x = fmaxf(v2.x + by.x, 0.f); o1.y = fmaxf(v2.y + by.y, 0.f);
            o1.z = fmaxf(v3.x + by.z, 0.f); o1.w = fmaxf(v3.y + by.w, 0.f);
            *(float4*)&Tsh[(r0 + i) * 132 + c0]     = o0;
            *(float4*)&Tsh[(r0 + i) * 132 + c0 + 4] = o1;
        }
    }
    __syncthreads();

    // ---- GEMM2: Tsh@W2 + b2 ----
    ZERO_ACC();
    for (int kk = 0; kk < D; kk += 16) {
        STAGE_W(w2);
        __syncthreads();
#pragma unroll
        for (int k4 = 0; k4 < 16; k4 += 4) {
            float4 a0 = *(const float4*)&Tsh[(r0 + 0) * 132 + kk + k4];
            float4 a1 = *(const float4*)&Tsh[(r0 + 1) * 132 + kk + k4];
            float4 a2 = *(const float4*)&Tsh[(r0 + 2) * 132 + kk + k4];
            float4 a3 = *(const float4*)&Tsh[(r0 + 3) * 132 + kk + k4];
            K_STEP(0, a0.x, a1.x, a2.x, a3.x)
            K_STEP(1, a0.y, a1.y, a2.y, a3.y)
            K_STEP(2, a0.z, a1.z, a2.z, a3.z)
            K_STEP(3, a0.w, a1.w, a2.w, a3.w)
        }
        __syncthreads();
    }
    {
        float4 bx = *(const float4*)(b2 + c0);
        float4 by = *(const float4*)(b2 + c0 + 4);
        float g0 = gam[0];
#pragma unroll
        for (int i = 0; i < 4; i++) {
            int m = blockRow + r0 + i;
            if (m < NN) {
                float so = g_rs_out[m];
                float2 v0 = up2(acc[i][0]);
                float2 v1 = up2(acc[i][1]);
                float2 v2 = up2(acc[i][2]);
                float2 v3 = up2(acc[i][3]);
                float h[8] = { v0.x + bx.x, v0.y + bx.y, v1.x + bx.z, v1.y + bx.w,
                               v2.x + by.x, v2.y + by.y, v3.x + by.z, v3.y + by.w };
                float4 rA, rB, sA, sB;
                rA.x = g0 * h[0]; rA.y = g0 * h[1]; rA.z = g0 * h[2]; rA.w = g0 * h[3];
                rB.x = g0 * h[4]; rB.y = g0 * h[5]; rB.z = g0 * h[6]; rB.w = g0 * h[7];
                sA.x = so * h[0]; sA.y = so * h[1]; sA.z = so * h[2]; sA.w = so * h[3];
                sB.x = so * h[4]; sB.y = so * h[5]; sB.z = so * h[6]; sB.w = so * h[7];
                *(float4*)(rep + (size_t)m * D + c0)     = rA;
                *(float4*)(rep + (size_t)m * D + c0 + 4) = rB;
                *(float4*)(hs  + (size_t)m * D + c0)     = sA;
                *(float4*)(hs  + (size_t)m * D + c0 + 4) = sB;
            }
        }
    }
}

// ---------------- graph conv: warp per dst node ----------------
__global__ void aggregate_kernel(const float* __restrict__ hin, float* __restrict__ hout,
                                 const float* __restrict__ gamma, int l, int last) {
    int w    = (blockIdx.x * blockDim.x + threadIdx.x) >> 5;
    int lane = threadIdx.x & 31;
    if (w >= NN) return;
    int beg = g_row_ptr[w];
    int end = g_row_ptr[w + 1];
    float4 acc = make_float4(0.f, 0.f, 0.f, 0.f);
    for (int e = beg; e < end; e++) {
        int s = g_col[e];
        float4 v = *(const float4*)&hin[(size_t)s * D + lane * 4];
        acc.x += v.x; acc.y += v.y; acc.z += v.z; acc.w += v.w;
    }
    float rin = g_rs_in[w];
    float gl  = gamma[l + 1] * rin;
    size_t off = (size_t)w * D + lane * 4;
    float4 rp = *(float4*)&g_rep[off];
    rp.x += gl * acc.x; rp.y += gl * acc.y; rp.z += gl * acc.z; rp.w += gl * acc.w;
    *(float4*)&g_rep[off] = rp;
    if (!last) {
        float s2 = rin * g_rs_out[w];
        float4 hn;
        hn.x = s2 * acc.x; hn.y = s2 * acc.y; hn.z = s2 * acc.z; hn.w = s2 * acc.w;
        *(float4*)&hout[off] = hn;
    }
}

// ---------------- fused predictor ----------------
// out = relu(relu((rep[s]*rep[d])@W1+b1)@W2+b2)@w3 + b3.  64 edges/block.
__global__ __launch_bounds__(256) void pred_kernel(
        const int* __restrict__ ps, const int* __restrict__ pd,
        const int* __restrict__ ns, const int* __restrict__ nd,
        const float* __restrict__ w1, const float* __restrict__ b1,
        const float* __restrict__ w2, const float* __restrict__ b2,
        const float* __restrict__ w3, const float* __restrict__ b3,
        const float* __restrict__ rep, float* __restrict__ out) {
    __shared__ __align__(16) float Esh[64 * 132];
    __shared__ __align__(16) float Wsh[16 * 128];
    __shared__ int sidx[64], didx[64];

    const int tid = threadIdx.x;
    const int c0  = (tid & 15) * 8;
    const int r0  = (tid >> 4) * 4;
    const int base = blockIdx.x * 64;

    if (tid < 64) {
        int w = base + tid;
        int s, d;
        if (w < PP) { s = ps[w]; d = pd[w]; }
        else        { s = ns[w - PP]; d = nd[w - PP]; }
        sidx[tid] = s; didx[tid] = d;
    }
    __syncthreads();

    // gather + elementwise multiply -> Esh
#pragma unroll
    for (int it = 0; it < 8; it++) {
        int c  = tid + it * 256;
        int r  = c >> 5;
        int c4 = c & 31;
        float4 a = *(const float4*)(rep + (size_t)sidx[r] * D + c4 * 4);
        float4 b = *(const float4*)(rep + (size_t)didx[r] * D + c4 * 4);
        float4 o;
        o.x = a.x * b.x; o.y = a.y * b.y; o.z = a.z * b.z; o.w = a.w * b.w;
        *(float4*)&Esh[r * 132 + c4 * 4] = o;
    }
    __syncthreads();

    ull acc[4][4];

    // ---- layer 1 ----
    ZERO_ACC();
    for (int kk = 0; kk < D; kk += 16) {
        STAGE_W(w1);
        __syncthreads();
#pragma unroll
        for (int k4 = 0; k4 < 16; k4 += 4) {
            float4 a0 = *(const float4*)&Esh[(r0 + 0) * 132 + kk + k4];
            float4 a1 = *(const float4*)&Esh[(r0 + 1) * 132 + kk + k4];
            float4 a2 = *(const float4*)&Esh[(r0 + 2) * 132 + kk + k4];
            float4 a3 = *(const float4*)&Esh[(r0 + 3) * 132 + kk + k4];
            K_STEP(0, a0.x, a1.x, a2.x, a3.x)
            K_STEP(1, a0.y, a1.y, a2.y, a3.y)
            K_STEP(2, a0.z, a1.z, a2.z, a3.z)
            K_STEP(3, a0.w, a1.w, a2.w, a3.w)
        }
        __syncthreads();
    }
    {
        float4 bx = *(const float4*)(b1 + c0);
        float4 by = *(const float4*)(b1 + c0 + 4);
#pragma unroll
        for (int i = 0; i < 4; i++) {
            float2 v0 = up2(acc[i][0]);
            float2 v1 = up2(acc[i][1]);
            float2 v2 = up2(acc[i][2]);
            float2 v3 = up2(acc[i][3]);
            float4 o0, o1;
            o0.x = fmaxf(v0.x + bx.x, 0.f); o0.y = fmaxf(v0.y + bx.y, 0.f);
            o0.z = fmaxf(v1.x + bx.z, 0.f); o0.w = fmaxf(v1.y + bx.w, 0.f);
            o1.x = fmaxf(v2.x + by.x, 0.f); o1.y = fmaxf(v2.y + by.y, 0.f);
            o1.z = fmaxf(v3.x + by.z, 0.f); o1.w = fmaxf(v3.y + by.w, 0.f);
            *(float4*)&Esh[(r0 + i) * 132 + c0]     = o0;
            *(float4*)&Esh[(r0 + i) * 132 + c0 + 4] = o1;
        }
    }
    __syncthreads();

    // ---- layer 2 ----
    ZERO_ACC();
    for (int kk = 0; kk < D; kk += 16) {
        STAGE_W(w2);
        __syncthreads();
#pragma unroll
        for (int k4 = 0; k4 < 16; k4 += 4) {
            float4 a0 = *(const float4*)&Esh[(r0 + 0) * 132 + kk + k4];
            float4 a1 = *(const float4*)&Esh[(r0 + 1) * 132 + kk + k4];
            float4 a2 = *(const float4*)&Esh[(r0 + 2) * 132 + kk + k4];
            float4 a3 = *(const float4*)&Esh[(r0 + 3) * 132 + kk + k4];
            K_STEP(0, a0.x, a1.x, a2.x, a3.x)
            K_STEP(1, a0.y, a1.y, a2.y, a3.y)
            K_STEP(2, a0.z, a1.z, a2.z, a3.z)
            K_STEP(3, a0.w, a1.w, a2.w, a3.w)
        }
        __syncthreads();
    }

    // ---- layer 3: relu, dot with w3, 16-lane reduce ----
    {
        float4 bx = *(const float4*)(b2 + c0);
        float4 by = *(const float4*)(b2 + c0 + 4);
        float4 wx = *(const float4*)(w3 + c0);
        float4 wy = *(const float4*)(w3 + c0 + 4);
        float bb3 = b3[0];
#pragma unroll
        for (int i = 0; i < 4; i++) {
            float2 v0 = up2(acc[i][0]);
            float2 v1 = up2(acc[i][1]);
            float2 v2 = up2(acc[i][2]);
            float2 v3 = up2(acc[i][3]);
            float p = fmaxf(v0.x + bx.x, 0.f) * wx.x
                    + fmaxf(v0.y + bx.y, 0.f) * wx.y
                    + fmaxf(v1.x + bx.z, 0.f) * wx.z
                    + fmaxf(v1.y + bx.w, 0.f) * wx.w
                    + fmaxf(v2.x + by.x, 0.f) * wy.x
                    + fmaxf(v2.y + by.y, 0.f) * wy.y
                    + fmaxf(v3.x + by.z, 0.f) * wy.z
                    + fmaxf(v3.y + by.w, 0.f) * wy.w;
#pragma unroll
            for (int off = 8; off > 0; off >>= 1)
                p += __shfl_xor_sync(0xFFFFFFFFu, p, off);
            if ((tid & 15) == 0) out[base + r0 + i] = p + bb3;
        }
    }
}

// ---------------- launch ----------------
extern "C" void kernel_launch(void* const* d_in, const int* in_sizes, int n_in,
                              void* d_out, int out_size) {
    const float* x   = (const float*)d_in[0];
    const float* w1  = (const float*)d_in[1];
    const float* b1  = (const float*)d_in[2];
    const float* w2  = (const float*)d_in[3];
    const float* b2  = (const float*)d_in[4];
    const float* gam = (const float*)d_in[5];
    const float* pw1 = (const float*)d_in[6];
    const float* pb1 = (const float*)d_in[7];
    const float* pw2 = (const float*)d_in[8];
    const float* pb2 = (const float*)d_in[9];
    const float* pw3 = (const float*)d_in[10];
    const float* pb3 = (const float*)d_in[11];
    const int* src = (const int*)d_in[12];
    const int* dst = (const int*)d_in[13];
    const int* ps  = (const int*)d_in[14];
    const int* pd  = (const int*)d_in[15];
    const int* ns  = (const int*)d_in[16];
    const int* nd  = (const int*)d_in[17];
    float* out = (float*)d_out;

    void *vA, *vB, *vrep;
    cudaGetSymbolAddress(&vA,   g_hA);
    cudaGetSymbolAddress(&vB,   g_hB);
    cudaGetSymbolAddress(&vrep, g_rep);
    float* hA  = (float*)vA;
    float* hB  = (float*)vB;
    float* rep = (float*)vrep;

    const int TB = 256;
    zero_cnt_kernel<<<NB, TB>>>();
    count_deg_kernel<<<(EE + TB - 1) / TB, TB>>>(src, dst);
    scanA_kernel<<<NB, TB>>>();
    scanB_kernel<<<1, 512>>>();
    scanC_kernel<<<NB, TB>>>();
    scatter_edges_kernel<<<(EE + TB - 1) / TB, TB>>>(src, dst);

    mlp_kernel<<<(NN + 63) / 64, TB>>>(x, w1, b1, w2, b2, gam, hA, rep);

    aggregate_kernel<<<(NN * 32 + TB - 1) / TB, TB>>>(hA, hB, gam, 0, 0);
    aggregate_kernel<<<(NN * 32 + TB - 1) / TB, TB>>>(hB, hA, gam, 1, 0);
    aggregate_kernel<<<(NN * 32 + TB - 1) / TB, TB>>>(hA, hB, gam, 2, 1);

    pred_kernel<<<(2 * PP) / 64, TB>>>(ps, pd, ns, nd, pw1, pb1, pw2, pb2, pw3, pb3, rep, out);
}

// round 5
// speedup vs baseline: 1.9533x; 1.9533x over previous
#include <cuda_runtime.h>
#include <cuda_bf16.h>
#include <cstdint>

#define NN 100000
#define EE 1600000
#define PP 100000
#define D  128
#define NB 391   // ceil(NN/256)

// ---- smem layout (bytes) ----
#define ROWP     272            // 136 bf16 per row (128 used + pad)
#define AH_OFF   0              // A hi : 64 x ROWP
#define AL_OFF   17408
#define WH_OFF   34816          // W hi : 128 x ROWP
#define WL_OFF   69632
#define SIDX_OFF 104448
#define DIDX_OFF 104704
#define PART_OFF 104960         // 2 x 64 floats
#define SMEM_TOT 105472

// ================= scratch (device globals; no allocation) =================
__device__ __align__(128) float g_hA [(size_t)NN * D];
__device__ __align__(128) float g_hB [(size_t)NN * D];
__device__ __align__(128) float g_rep[(size_t)NN * D];
__device__ int   g_cnt_in [NN];
__device__ int   g_cnt_out[NN];
__device__ float g_rs_in  [NN];
__device__ float g_rs_out [NN];
__device__ int   g_row_ptr[NN + 1];
__device__ int   g_cursor [NN];
__device__ int   g_col    [EE];
__device__ int   g_bsum   [NB];
__device__ int   g_boff   [NB];

// ================= graph structure (unchanged, measured-good) ==============
__global__ void zero_cnt_kernel() {
    int v = blockIdx.x * blockDim.x + threadIdx.x;
    if (v < NN) { g_cnt_in[v] = 0; g_cnt_out[v] = 0; }
}

__global__ void count_deg_kernel(const int* __restrict__ src, const int* __restrict__ dst) {
    int e = blockIdx.x * blockDim.x + threadIdx.x;
    if (e < EE) {
        atomicAdd(&g_cnt_out[src[e]], 1);
        atomicAdd(&g_cnt_in [dst[e]], 1);
    }
}

__global__ void scanA_kernel() {
    __shared__ int sh[256];
    int i = blockIdx.x * 256 + threadIdx.x;
    int v = (i < NN) ? g_cnt_in[i] : 0;
    sh[threadIdx.x] = v;
    __syncthreads();
    for (int off = 128; off > 0; off >>= 1) {
        if (threadIdx.x < off) sh[threadIdx.x] += sh[threadIdx.x + off];
        __syncthreads();
    }
    if (threadIdx.x == 0) g_bsum[blockIdx.x] = sh[0];
}

__global__ void scanB_kernel() {
    __shared__ int sh[512];
    int t = threadIdx.x;
    int v = (t < NB) ? g_bsum[t] : 0;
    sh[t] = v;
    __syncthreads();
    for (int off = 1; off < 512; off <<= 1) {
        int x = (t >= off) ? sh[t - off] : 0;
        __syncthreads();
        sh[t] += x;
        __syncthreads();
    }
    if (t < NB) g_boff[t] = sh[t] - v;
}

__global__ void scanC_kernel() {
    __shared__ int sh[256];
    int b = blockIdx.x;
    int i = b * 256 + threadIdx.x;
    int v = (i < NN) ? g_cnt_in[i] : 0;
    sh[threadIdx.x] = v;
    __syncthreads();
    for (int off = 1; off < 256; off <<= 1) {
        int x = (threadIdx.x >= off) ? sh[threadIdx.x - off] : 0;
        __syncthreads();
        sh[threadIdx.x] += x;
        __syncthreads();
    }
    if (i < NN) {
        int incl = g_boff[b] + sh[threadIdx.x];
        g_row_ptr[i + 1] = incl;
        g_cursor[i] = incl - v;
        int ci = v; if (ci < 1) ci = 1;
        int co = g_cnt_out[i]; if (co < 1) co = 1;
        g_rs_in [i] = rsqrtf((float)ci);
        g_rs_out[i] = rsqrtf((float)co);
        if (i == 0) g_row_ptr[0] = 0;
    }
}

__global__ void scatter_edges_kernel(const int* __restrict__ src, const int* __restrict__ dst) {
    int e = blockIdx.x * blockDim.x + threadIdx.x;
    if (e < EE) {
        int pos = atomicAdd(&g_cursor[dst[e]], 1);
        g_col[pos] = src[e];
    }
}

// ================= graph conv (unchanged from R2) ===========================
__global__ void aggregate_kernel(const float* __restrict__ hin, float* __restrict__ hout,
                                 const float* __restrict__ gamma, int l, int last) {
    int w    = (blockIdx.x * blockDim.x + threadIdx.x) >> 5;
    int lane = threadIdx.x & 31;
    if (w >= NN) return;
    int beg = g_row_ptr[w];
    int end = g_row_ptr[w + 1];
    float4 acc = make_float4(0.f, 0.f, 0.f, 0.f);
    for (int e = beg; e < end; e++) {
        int s = g_col[e];
        float4 v = *(const float4*)&hin[(size_t)s * D + lane * 4];
        acc.x += v.x; acc.y += v.y; acc.z += v.z; acc.w += v.w;
    }
    float rin = g_rs_in[w];
    float gl  = gamma[l + 1] * rin;
    size_t off = (size_t)w * D + lane * 4;
    float4 rp = *(float4*)&g_rep[off];
    rp.x += gl * acc.x; rp.y += gl * acc.y; rp.z += gl * acc.z; rp.w += gl * acc.w;
    *(float4*)&g_rep[off] = rp;
    if (!last) {
        float s2 = rin * g_rs_out[w];
        float4 hn;
        hn.x = s2 * acc.x; hn.y = s2 * acc.y; hn.z = s2 * acc.z; hn.w = s2 * acc.w;
        *(float4*)&hout[off] = hn;
    }
}

// ================= mma.sync plumbing (virtual-arch-safe PTX) ================
__device__ __forceinline__ uint32_t smem_u32(const void* p) {
    uint32_t a;
    asm("{ .reg .u64 t; cvta.to.shared.u64 t, %1; cvt.u32.u64 %0, t; }" : "=r"(a) : "l"(p));
    return a;
}

#define LDSM_X4(R, A)                                                        \
    asm volatile("ldmatrix.sync.aligned.m8n8.x4.shared.b16 {%0,%1,%2,%3}, [%4];" \
        : "=r"((R)[0]), "=r"((R)[1]), "=r"((R)[2]), "=r"((R)[3]) : "r"(A))

#define LDSM_X4T(R, A)                                                       \
    asm volatile("ldmatrix.sync.aligned.m8n8.x4.trans.shared.b16 {%0,%1,%2,%3}, [%4];" \
        : "=r"((R)[0]), "=r"((R)[1]), "=r"((R)[2]), "=r"((R)[3]) : "r"(A))

#define MMA16816(C, AR, B0, B1)                                              \
    asm volatile("mma.sync.aligned.m16n8k16.row.col.f32.bf16.bf16.f32 "      \
        "{%0,%1,%2,%3}, {%4,%5,%6,%7}, {%8,%9}, {%0,%1,%2,%3};"              \
        : "+f"((C)[0]), "+f"((C)[1]), "+f"((C)[2]), "+f"((C)[3])             \
        : "r"((AR)[0]), "r"((AR)[1]), "r"((AR)[2]), "r"((AR)[3]),            \
          "r"(B0), "r"(B1))

__device__ __forceinline__ void split_bf(float v, unsigned& h, unsigned& l) {
    __nv_bfloat16 hb = __float2bfloat16(v);
    float r = v - __bfloat162float(hb);
    __nv_bfloat16 lb = __float2bfloat16(r);
    h = (unsigned)__bfloat16_as_ushort(hb);
    l = (unsigned)__bfloat16_as_ushort(lb);
}
__device__ __forceinline__ void split4(float4 v, uint2& hi, uint2& lo) {
    unsigned h0, h1, h2, h3, l0, l1, l2, l3;
    split_bf(v.x, h0, l0);
    split_bf(v.y, h1, l1);
    split_bf(v.z, h2, l2);
    split_bf(v.w, h3, l3);
    hi.x = h0 | (h1 << 16); hi.y = h2 | (h3 << 16);
    lo.x = l0 | (l1 << 16); lo.y = l2 | (l3 << 16);
}

// stage 128x128 f32 row-major weight into W hi/lo bf16 smem tiles ([k][n])
__device__ __forceinline__ void stage_W(const float* __restrict__ W, char* sm, int tid) {
#pragma unroll
    for (int it = 0; it < 16; it++) {
        int idx4 = tid + it * 256;      // 0..4095
        int k  = idx4 >> 5;
        int c4 = idx4 & 31;
        float4 v = *(const float4*)(W + (size_t)k * 128 + c4 * 4);
        uint2 hi, lo;
        split4(v, hi, lo);
        *(uint2*)(sm + WH_OFF + k * ROWP + c4 * 8) = hi;
        *(uint2*)(sm + WL_OFF + k * ROWP + c4 * 8) = lo;
    }
}

// 64x128 GEMM core: acc[nt][..] over warp tile 16x64; 3-pass bf16 split
__device__ __forceinline__ void gemm_core(uint32_t sb, float acc[8][4],
                                          int wm, int wn, int lane) {
#pragma unroll
    for (int i = 0; i < 8; i++)
#pragma unroll
        for (int j = 0; j < 4; j++) acc[i][j] = 0.f;

    const uint32_t a_addr = sb + AH_OFF + (uint32_t)(wm + (lane & 15)) * ROWP
                            + ((lane >> 4) << 4);
    const uint32_t b_row  = (uint32_t)(lane & 15) * ROWP;
    const uint32_t b_col  = (uint32_t)wn * 2 + ((lane >> 4) << 4);

#pragma unroll
    for (int ks = 0; ks < 8; ks++) {
        uint32_t ah[4], al[4];
        LDSM_X4(ah, a_addr + ks * 32);
        LDSM_X4(al, a_addr + ks * 32 + (AL_OFF - AH_OFF));
        uint32_t bbase = sb + WH_OFF + (uint32_t)(ks * 16) * ROWP + b_row + b_col;
#pragma unroll
        for (int g = 0; g < 4; g++) {
            uint32_t bh[4], bl[4];
            uint32_t ba = bbase + g * 32;
            LDSM_X4T(bh, ba);
            LDSM_X4T(bl, ba + (WL_OFF - WH_OFF));
            MMA16816(acc[2 * g],     ah, bh[0], bh[1]);
            MMA16816(acc[2 * g + 1], ah, bh[2], bh[3]);
            MMA16816(acc[2 * g],     ah, bl[0], bl[1]);
            MMA16816(acc[2 * g + 1], ah, bl[2], bl[3]);
            MMA16816(acc[2 * g],     al, bh[0], bh[1]);
            MMA16816(acc[2 * g + 1], al, bh[2], bh[3]);
        }
    }
}

// epilogue helper: relu(acc + bias) -> write back into A smem tiles (bf16 hi/lo)
__device__ __forceinline__ void epi_to_A(char* sm, float acc[8][4],
                                         const float* __restrict__ bias,
                                         int wm, int wn, int lane) {
    int r0 = wm + (lane >> 2);
    int r1 = r0 + 8;
#pragma unroll
    for (int nt = 0; nt < 8; nt++) {
        int c = wn + nt * 8 + 2 * (lane & 3);
        float2 bv = *(const float2*)(bias + c);
        float v0 = fmaxf(acc[nt][0] + bv.x, 0.f);
        float v1 = fmaxf(acc[nt][1] + bv.y, 0.f);
        float v2 = fmaxf(acc[nt][2] + bv.x, 0.f);
        float v3 = fmaxf(acc[nt][3] + bv.y, 0.f);
        unsigned h0, h1, h2, h3, l0, l1, l2, l3;
        split_bf(v0, h0, l0); split_bf(v1, h1, l1);
        split_bf(v2, h2, l2); split_bf(v3, h3, l3);
        *(uint32_t*)(sm + AH_OFF + r0 * ROWP + c * 2) = h0 | (h1 << 16);
        *(uint32_t*)(sm + AL_OFF + r0 * ROWP + c * 2) = l0 | (l1 << 16);
        *(uint32_t*)(sm + AH_OFF + r1 * ROWP + c * 2) = h2 | (h3 << 16);
        *(uint32_t*)(sm + AL_OFF + r1 * ROWP + c * 2) = l2 | (l3 << 16);
    }
}

// ================= fused node MLP (tensor cores, mma.sync) ==================
__global__ __launch_bounds__(256) void mlp_mma_kernel(
        const float* __restrict__ x,
        const float* __restrict__ w1, const float* __restrict__ b1,
        const float* __restrict__ w2, const float* __restrict__ b2,
        const float* __restrict__ gam,
        float* __restrict__ hs, float* __restrict__ rep) {
    extern __shared__ char sm[];
    const uint32_t sb = smem_u32(sm);
    const int tid  = threadIdx.x;
    const int wid  = tid >> 5;
    const int lane = tid & 31;
    const int wm   = (wid & 3) * 16;
    const int wn   = (wid >> 2) * 64;
    const int blockRow = blockIdx.x * 64;

    // stage A = x rows (hi/lo split)
#pragma unroll
    for (int it = 0; it < 8; it++) {
        int idx4 = tid + it * 256;      // 0..2047
        int r  = idx4 >> 5;
        int c4 = idx4 & 31;
        float4 v = make_float4(0.f, 0.f, 0.f, 0.f);
        if (blockRow + r < NN)
            v = *(const float4*)(x + (size_t)(blockRow + r) * D + c4 * 4);
        uint2 hi, lo;
        split4(v, hi, lo);
        *(uint2*)(sm + AH_OFF + r * ROWP + c4 * 8) = hi;
        *(uint2*)(sm + AL_OFF + r * ROWP + c4 * 8) = lo;
    }
    stage_W(w1, sm, tid);
    __syncthreads();

    float acc[8][4];
    gemm_core(sb, acc, wm, wn, lane);
    __syncthreads();

    epi_to_A(sm, acc, b1, wm, wn, lane);
    stage_W(w2, sm, tid);
    __syncthreads();

    gemm_core(sb, acc, wm, wn, lane);

    // epilogue 2: h = acc + b2 ; rep = g0*h ; hs = rs_out*h
    {
        float g0 = gam[0];
        int r0 = blockRow + wm + (lane >> 2);
        int r1 = r0 + 8;
        bool ok0 = (r0 < NN), ok1 = (r1 < NN);
        float so0 = ok0 ? g_rs_out[r0] : 0.f;
        float so1 = ok1 ? g_rs_out[r1] : 0.f;
#pragma unroll
        for (int nt = 0; nt < 8; nt++) {
            int c = wn + nt * 8 + 2 * (lane & 3);
            float2 bv = *(const float2*)(b2 + c);
            if (ok0) {
                float h0 = acc[nt][0] + bv.x;
                float h1 = acc[nt][1] + bv.y;
                float2 rv = make_float2(g0 * h0, g0 * h1);
                float2 sv = make_float2(so0 * h0, so0 * h1);
                *(float2*)(rep + (size_t)r0 * D + c) = rv;
                *(float2*)(hs  + (size_t)r0 * D + c) = sv;
            }
            if (ok1) {
                float h2 = acc[nt][2] + bv.x;
                float h3 = acc[nt][3] + bv.y;
                float2 rv = make_float2(g0 * h2, g0 * h3);
                float2 sv = make_float2(so1 * h2, so1 * h3);
                *(float2*)(rep + (size_t)r1 * D + c) = rv;
                *(float2*)(hs  + (size_t)r1 * D + c) = sv;
            }
        }
    }
}

// ================= fused predictor (tensor cores, mma.sync) =================
__global__ __launch_bounds__(256) void pred_mma_kernel(
        const int* __restrict__ ps, const int* __restrict__ pd,
        const int* __restrict__ ns, const int* __restrict__ nd,
        const float* __restrict__ w1, const float* __restrict__ b1,
        const float* __restrict__ w2, const float* __restrict__ b2,
        const float* __restrict__ w3, const float* __restrict__ b3,
        const float* __restrict__ rep, float* __restrict__ out) {
    extern __shared__ char sm[];
    const uint32_t sb = smem_u32(sm);
    const int tid  = threadIdx.x;
    const int wid  = tid >> 5;
    const int lane = tid & 31;
    const int wm   = (wid & 3) * 16;
    const int wn   = (wid >> 2) * 64;
    const int base = blockIdx.x * 64;

    int* sidx = (int*)(sm + SIDX_OFF);
    int* didx = (int*)(sm + DIDX_OFF);
    float* part = (float*)(sm + PART_OFF);

    if (tid < 64) {
        int w = base + tid;    // 2*PP divisible by 64 -> always valid
        int s, d;
        if (w < PP) { s = ps[w]; d = pd[w]; }
        else        { s = ns[w - PP]; d = nd[w - PP]; }
        sidx[tid] = s; didx[tid] = d;
    }
    __syncthreads();

    // stage E = rep[s]*rep[d] (hi/lo split)
#pragma unroll
    for (int it = 0; it < 8; it++) {
        int idx4 = tid + it * 256;
        int r  = idx4 >> 5;
        int c4 = idx4 & 31;
        float4 a = *(const float4*)(rep + (size_t)sidx[r] * D + c4 * 4);
        float4 b = *(const float4*)(rep + (size_t)didx[r] * D + c4 * 4);
        float4 v;
        v.x = a.x * b.x; v.y = a.y * b.y; v.z = a.z * b.z; v.w = a.w * b.w;
        uint2 hi, lo;
        split4(v, hi, lo);
        *(uint2*)(sm + AH_OFF + r * ROWP + c4 * 8) = hi;
        *(uint2*)(sm + AL_OFF + r * ROWP + c4 * 8) = lo;
    }
    stage_W(w1, sm, tid);
    __syncthreads();

    float acc[8][4];
    gemm_core(sb, acc, wm, wn, lane);
    __syncthreads();

    epi_to_A(sm, acc, b1, wm, wn, lane);
    stage_W(w2, sm, tid);
    __syncthreads();

    gemm_core(sb, acc, wm, wn, lane);

    // epilogue: p = sum_c relu(acc + b2[c]) * w3[c], reduce, write out
    {
        float p0 = 0.f, p1 = 0.f;
#pragma unroll
        for (int nt = 0; nt < 8; nt++) {
            int c = wn + nt * 8 + 2 * (lane & 3);
            float2 bv = *(const float2*)(b2 + c);
            float2 wv = *(const float2*)(w3 + c);
            p0 += fmaxf(acc[nt][0] + bv.x, 0.f) * wv.x
                + fmaxf(acc[nt][1] + bv.y, 0.f) * wv.y;
            p1 += fmaxf(acc[nt][2] + bv.x, 0.f) * wv.x
                + fmaxf(acc[nt][3] + bv.y, 0.f) * wv.y;
        }
        p0 += __shfl_xor_sync(0xFFFFFFFFu, p0, 1);
        p0 += __shfl_xor_sync(0xFFFFFFFFu, p0, 2);
        p1 += __shfl_xor_sync(0xFFFFFFFFu, p1, 1);
        p1 += __shfl_xor_sync(0xFFFFFFFFu, p1, 2);
        if ((lane & 3) == 0) {
            int g = (wn >> 6);             // 0 or 1
            int rl = wm + (lane >> 2);
            part[g * 64 + rl]     = p0;
            part[g * 64 + rl + 8] = p1;
        }
    }
    __syncthreads();
    if (tid < 64) {
        out[base + tid] = part[tid] + part[64 + tid] + b3[0];
    }
}

// ================= launch ===================================================
extern "C" void kernel_launch(void* const* d_in, const int* in_sizes, int n_in,
                              void* d_out, int out_size) {
    const float* x   = (const float*)d_in[0];
    const float* w1  = (const float*)d_in[1];
    const float* b1  = (const float*)d_in[2];
    const float* w2  = (const float*)d_in[3];
    const float* b2  = (const float*)d_in[4];
    const float* gam = (const float*)d_in[5];
    const float* pw1 = (const float*)d_in[6];
    const float* pb1 = (const float*)d_in[7];
    const float* pw2 = (const float*)d_in[8];
    const float* pb2 = (const float*)d_in[9];
    const float* pw3 = (const float*)d_in[10];
    const float* pb3 = (const float*)d_in[11];
    const int* src = (const int*)d_in[12];
    const int* dst = (const int*)d_in[13];
    const int* ps  = (const int*)d_in[14];
    const int* pd  = (const int*)d_in[15];
    const int* ns  = (const int*)d_in[16];
    const int* nd  = (const int*)d_in[17];
    float* out = (float*)d_out;

    void *vA, *vB, *vrep;
    cudaGetSymbolAddress(&vA,   g_hA);
    cudaGetSymbolAddress(&vB,   g_hB);
    cudaGetSymbolAddress(&vrep, g_rep);
    float* hA  = (float*)vA;
    float* hB  = (float*)vB;
    float* rep = (float*)vrep;

    cudaFuncSetAttribute(mlp_mma_kernel,  cudaFuncAttributeMaxDynamicSharedMemorySize, SMEM_TOT);
    cudaFuncSetAttribute(pred_mma_kernel, cudaFuncAttributeMaxDynamicSharedMemorySize, SMEM_TOT);

    const int TB = 256;
    zero_cnt_kernel<<<NB, TB>>>();
    count_deg_kernel<<<(EE + TB - 1) / TB, TB>>>(src, dst);
    scanA_kernel<<<NB, TB>>>();
    scanB_kernel<<<1, 512>>>();
    scanC_kernel<<<NB, TB>>>();
    scatter_edges_kernel<<<(EE + TB - 1) / TB, TB>>>(src, dst);

    mlp_mma_kernel<<<(NN + 63) / 64, TB, SMEM_TOT>>>(x, w1, b1, w2, b2, gam, hA, rep);

    aggregate_kernel<<<(NN * 32 + TB - 1) / TB, TB>>>(hA, hB, gam, 0, 0);
    aggregate_kernel<<<(NN * 32 + TB - 1) / TB, TB>>>(hB, hA, gam, 1, 0);
    aggregate_kernel<<<(NN * 32 + TB - 1) / TB, TB>>>(hA, hB, gam, 2, 1);

    pred_mma_kernel<<<(2 * PP) / 64, TB, SMEM_TOT>>>(
        ps, pd, ns, nd, pw1, pb1, pw2, pb2, pw3, pb3, rep, out);
}

// round 6
// speedup vs baseline: 2.0244x; 1.0364x over previous
#include <cuda_runtime.h>
#include <cuda_bf16.h>
#include <cstdint>

#define NN 100000
#define EE 1600000
#define PP 100000
#define D  128
#define NB 391   // ceil(NN/256)

// ---- smem layout (bytes) ----
#define ROWP     272            // 136 bf16 per row (128 used + pad)
#define AH_OFF   0              // A hi : 64 x ROWP
#define AL_OFF   17408
#define WH_OFF   34816          // W hi : 128 x ROWP
#define WL_OFF   69632          // contiguous after WH
#define SIDX_OFF 104448
#define DIDX_OFF 104704
#define PART_OFF 104960         // 2 x 64 floats
#define SMEM_TOT 105472

#define WTILE_B  34816          // 128 * ROWP

// ================= scratch (device globals; no allocation) =================
__device__ __align__(128) float g_hA [(size_t)NN * D];
__device__ __align__(128) float g_hB [(size_t)NN * D];
__device__ __align__(128) float g_rep[(size_t)NN * D];
__device__ __align__(16)  char  g_wt [4][2][WTILE_B];   // w1,w2,pw1,pw2 hi/lo
__device__ int   g_cnt_in [NN];
__device__ int   g_cnt_out[NN];
__device__ float g_rs_in  [NN];
__device__ float g_rs_out [NN];
__device__ int   g_row_ptr[NN + 1];
__device__ int   g_cursor [NN];
__device__ int   g_col    [EE];
__device__ int   g_bsum   [NB];
__device__ int   g_boff   [NB];

// ================= graph structure (unchanged, measured-good) ==============
__global__ void zero_cnt_kernel() {
    int v = blockIdx.x * blockDim.x + threadIdx.x;
    if (v < NN) { g_cnt_in[v] = 0; g_cnt_out[v] = 0; }
}

__global__ void count_deg_kernel(const int* __restrict__ src, const int* __restrict__ dst) {
    int e = blockIdx.x * blockDim.x + threadIdx.x;
    if (e < EE) {
        atomicAdd(&g_cnt_out[src[e]], 1);
        atomicAdd(&g_cnt_in [dst[e]], 1);
    }
}

__global__ void scanA_kernel() {
    __shared__ int sh[256];
    int i = blockIdx.x * 256 + threadIdx.x;
    int v = (i < NN) ? g_cnt_in[i] : 0;
    sh[threadIdx.x] = v;
    __syncthreads();
    for (int off = 128; off > 0; off >>= 1) {
        if (threadIdx.x < off) sh[threadIdx.x] += sh[threadIdx.x + off];
        __syncthreads();
    }
    if (threadIdx.x == 0) g_bsum[blockIdx.x] = sh[0];
}

__global__ void scanB_kernel() {
    __shared__ int sh[512];
    int t = threadIdx.x;
    int v = (t < NB) ? g_bsum[t] : 0;
    sh[t] = v;
    __syncthreads();
    for (int off = 1; off < 512; off <<= 1) {
        int x = (t >= off) ? sh[t - off] : 0;
        __syncthreads();
        sh[t] += x;
        __syncthreads();
    }
    if (t < NB) g_boff[t] = sh[t] - v;
}

__global__ void scanC_kernel() {
    __shared__ int sh[256];
    int b = blockIdx.x;
    int i = b * 256 + threadIdx.x;
    int v = (i < NN) ? g_cnt_in[i] : 0;
    sh[threadIdx.x] = v;
    __syncthreads();
    for (int off = 1; off < 256; off <<= 1) {
        int x = (threadIdx.x >= off) ? sh[threadIdx.x - off] : 0;
        __syncthreads();
        sh[threadIdx.x] += x;
        __syncthreads();
    }
    if (i < NN) {
        int incl = g_boff[b] + sh[threadIdx.x];
        g_row_ptr[i + 1] = incl;
        g_cursor[i] = incl - v;
        int ci = v; if (ci < 1) ci = 1;
        int co = g_cnt_out[i]; if (co < 1) co = 1;
        g_rs_in [i] = rsqrtf((float)ci);
        g_rs_out[i] = rsqrtf((float)co);
        if (i == 0) g_row_ptr[0] = 0;
    }
}

__global__ void scatter_edges_kernel(const int* __restrict__ src, const int* __restrict__ dst) {
    int e = blockIdx.x * blockDim.x + threadIdx.x;
    if (e < EE) {
        int pos = atomicAdd(&g_cursor[dst[e]], 1);
        g_col[pos] = src[e];
    }
}

// ================= bf16 split helpers =======================================
__device__ __forceinline__ void split_bf(float v, unsigned& h, unsigned& l) {
    __nv_bfloat16 hb = __float2bfloat16(v);
    float r = v - __bfloat162float(hb);
    __nv_bfloat16 lb = __float2bfloat16(r);
    h = (unsigned)__bfloat16_as_ushort(hb);
    l = (unsigned)__bfloat16_as_ushort(lb);
}
__device__ __forceinline__ void split4(float4 v, uint2& hi, uint2& lo) {
    unsigned h0, h1, h2, h3, l0, l1, l2, l3;
    split_bf(v.x, h0, l0);
    split_bf(v.y, h1, l1);
    split_bf(v.z, h2, l2);
    split_bf(v.w, h3, l3);
    hi.x = h0 | (h1 << 16); hi.y = h2 | (h3 << 16);
    lo.x = l0 | (l1 << 16); lo.y = l2 | (l3 << 16);
}

// precompute padded bf16 hi/lo weight tiles (one block per weight matrix)
__global__ void prep_w_kernel(const float* __restrict__ w1, const float* __restrict__ w2,
                              const float* __restrict__ pw1, const float* __restrict__ pw2) {
    const float* W = (blockIdx.x == 0) ? w1 : (blockIdx.x == 1) ? w2
                   : (blockIdx.x == 2) ? pw1 : pw2;
    char* hiB = &g_wt[blockIdx.x][0][0];
    char* loB = &g_wt[blockIdx.x][1][0];
    int tid = threadIdx.x;
#pragma unroll
    for (int it = 0; it < 16; it++) {
        int idx4 = tid + it * 256;      // 0..4095
        int k  = idx4 >> 5;
        int c4 = idx4 & 31;
        float4 v = *(const float4*)(W + (size_t)k * 128 + c4 * 4);
        uint2 hi, lo;
        split4(v, hi, lo);
        *(uint2*)(hiB + k * ROWP + c4 * 8) = hi;
        *(uint2*)(loB + k * ROWP + c4 * 8) = lo;
    }
}

// ================= graph conv ===============================================
// SCALE_SRC: multiply gathered rows by rs_out[src] (used for layer 0, whose
// input h0 is stored unscaled so the MLP has no dependency on the CSR chain)
template <int SCALE_SRC, int LAST>
__global__ void aggregate_kernel(const float* __restrict__ hin, float* __restrict__ hout,
                                 const float* __restrict__ gamma, int l) {
    int w    = (blockIdx.x * blockDim.x + threadIdx.x) >> 5;
    int lane = threadIdx.x & 31;
    if (w >= NN) return;
    int beg = g_row_ptr[w];
    int end = g_row_ptr[w + 1];
    float4 acc = make_float4(0.f, 0.f, 0.f, 0.f);
    int e = beg;
    for (; e + 4 <= end; e += 4) {
        int s0 = g_col[e], s1 = g_col[e + 1], s2 = g_col[e + 2], s3 = g_col[e + 3];
        float4 v0 = *(const float4*)&hin[(size_t)s0 * D + lane * 4];
        float4 v1 = *(const float4*)&hin[(size_t)s1 * D + lane * 4];
        float4 v2 = *(const float4*)&hin[(size_t)s2 * D + lane * 4];
        float4 v3 = *(const float4*)&hin[(size_t)s3 * D + lane * 4];
        if (SCALE_SRC) {
            float m0 = g_rs_out[s0], m1 = g_rs_out[s1];
            float m2 = g_rs_out[s2], m3 = g_rs_out[s3];
            acc.x = fmaf(m0, v0.x, acc.x); acc.y = fmaf(m0, v0.y, acc.y);
            acc.z = fmaf(m0, v0.z, acc.z); acc.w = fmaf(m0, v0.w, acc.w);
            acc.x = fmaf(m1, v1.x, acc.x); acc.y = fmaf(m1, v1.y, acc.y);
            acc.z = fmaf(m1, v1.z, acc.z); acc.w = fmaf(m1, v1.w, acc.w);
            acc.x = fmaf(m2, v2.x, acc.x); acc.y = fmaf(m2, v2.y, acc.y);
            acc.z = fmaf(m2, v2.z, acc.z); acc.w = fmaf(m2, v2.w, acc.w);
            acc.x = fmaf(m3, v3.x, acc.x); acc.y = fmaf(m3, v3.y, acc.y);
            acc.z = fmaf(m3, v3.z, acc.z); acc.w = fmaf(m3, v3.w, acc.w);
        } else {
            acc.x += v0.x + v1.x + v2.x + v3.x;
            acc.y += v0.y + v1.y + v2.y + v3.y;
            acc.z += v0.z + v1.z + v2.z + v3.z;
            acc.w += v0.w + v1.w + v2.w + v3.w;
        }
    }
    for (; e < end; e++) {
        int s = g_col[e];
        float4 v = *(const float4*)&hin[(size_t)s * D + lane * 4];
        float m = SCALE_SRC ? g_rs_out[s] : 1.0f;
        acc.x = fmaf(m, v.x, acc.x); acc.y = fmaf(m, v.y, acc.y);
        acc.z = fmaf(m, v.z, acc.z); acc.w = fmaf(m, v.w, acc.w);
    }
    float rin = g_rs_in[w];
    float gl  = gamma[l + 1] * rin;
    size_t off = (size_t)w * D + lane * 4;
    float4 rp = __ldcs((const float4*)&g_rep[off]);       // streaming RMW
    rp.x += gl * acc.x; rp.y += gl * acc.y; rp.z += gl * acc.z; rp.w += gl * acc.w;
    __stcs((float4*)&g_rep[off], rp);
    if (!LAST) {
        float s2 = rin * g_rs_out[w];
        float4 hn;
        hn.x = s2 * acc.x; hn.y = s2 * acc.y; hn.z = s2 * acc.z; hn.w = s2 * acc.w;
        *(float4*)&hout[off] = hn;                        // keep L2-resident
    }
}

// ================= mma.sync plumbing (virtual-arch-safe PTX) ================
__device__ __forceinline__ uint32_t smem_u32(const void* p) {
    uint32_t a;
    asm("{ .reg .u64 t; cvta.to.shared.u64 t, %1; cvt.u32.u64 %0, t; }" : "=r"(a) : "l"(p));
    return a;
}

#define LDSM_X4(R, A)                                                        \
    asm volatile("ldmatrix.sync.aligned.m8n8.x4.shared.b16 {%0,%1,%2,%3}, [%4];" \
        : "=r"((R)[0]), "=r"((R)[1]), "=r"((R)[2]), "=r"((R)[3]) : "r"(A))

#define LDSM_X4T(R, A)                                                       \
    asm volatile("ldmatrix.sync.aligned.m8n8.x4.trans.shared.b16 {%0,%1,%2,%3}, [%4];" \
        : "=r"((R)[0]), "=r"((R)[1]), "=r"((R)[2]), "=r"((R)[3]) : "r"(A))

#define MMA16816(C, AR, B0, B1)                                              \
    asm volatile("mma.sync.aligned.m16n8k16.row.col.f32.bf16.bf16.f32 "      \
        "{%0,%1,%2,%3}, {%4,%5,%6,%7}, {%8,%9}, {%0,%1,%2,%3};"              \
        : "+f"((C)[0]), "+f"((C)[1]), "+f"((C)[2]), "+f"((C)[3])             \
        : "r"((AR)[0]), "r"((AR)[1]), "r"((AR)[2]), "r"((AR)[3]),            \
          "r"(B0), "r"(B1))

// copy precomputed hi+lo weight tile (69632 B contiguous) into smem
__device__ __forceinline__ void load_W(char* sm, int widx, int tid) {
    const uint4* src = (const uint4*)&g_wt[widx][0][0];
    uint4* dst = (uint4*)(sm + WH_OFF);
#pragma unroll
    for (int i = 0; i < 17; i++)          // 17*256 = 4352 uint4 = 69632 B
        dst[tid + i * 256] = src[tid + i * 256];
}

// 64x128 GEMM core: warp tile 16x64; 3-pass bf16 split
__device__ __forceinline__ void gemm_core(uint32_t sb, float acc[8][4],
                                          int wm, int wn, int lane) {
#pragma unroll
    for (int i = 0; i < 8; i++)
#pragma unroll
        for (int j = 0; j < 4; j++) acc[i][j] = 0.f;

    const uint32_t a_addr = sb + AH_OFF + (uint32_t)(wm + (lane & 15)) * ROWP
                            + ((lane >> 4) << 4);
    const uint32_t b_row  = (uint32_t)(lane & 15) * ROWP;
    const uint32_t b_col  = (uint32_t)wn * 2 + ((lane >> 4) << 4);

#pragma unroll
    for (int ks = 0; ks < 8; ks++) {
        uint32_t ah[4], al[4];
        LDSM_X4(ah, a_addr + ks * 32);
        LDSM_X4(al, a_addr + ks * 32 + (AL_OFF - AH_OFF));
        uint32_t bbase = sb + WH_OFF + (uint32_t)(ks * 16) * ROWP + b_row + b_col;
#pragma unroll
        for (int g = 0; g < 4; g++) {
            uint32_t bh[4], bl[4];
            uint32_t ba = bbase + g * 32;
            LDSM_X4T(bh, ba);
            LDSM_X4T(bl, ba + (WL_OFF - WH_OFF));
            MMA16816(acc[2 * g],     ah, bh[0], bh[1]);
            MMA16816(acc[2 * g + 1], ah, bh[2], bh[3]);
            MMA16816(acc[2 * g],     ah, bl[0], bl[1]);
            MMA16816(acc[2 * g + 1], ah, bl[2], bl[3]);
            MMA16816(acc[2 * g],     al, bh[0], bh[1]);
            MMA16816(acc[2 * g + 1], al, bh[2], bh[3]);
        }
    }
}

// relu(acc + bias) -> back into A smem tiles (bf16 hi/lo)
__device__ __forceinline__ void epi_to_A(char* sm, float acc[8][4],
                                         const float* __restrict__ bias,
                                         int wm, int wn, int lane) {
    int r0 = wm + (lane >> 2);
    int r1 = r0 + 8;
#pragma unroll
    for (int nt = 0; nt < 8; nt++) {
        int c = wn + nt * 8 + 2 * (lane & 3);
        float2 bv = *(const float2*)(bias + c);
        float v0 = fmaxf(acc[nt][0] + bv.x, 0.f);
        float v1 = fmaxf(acc[nt][1] + bv.y, 0.f);
        float v2 = fmaxf(acc[nt][2] + bv.x, 0.f);
        float v3 = fmaxf(acc[nt][3] + bv.y, 0.f);
        unsigned h0, h1, h2, h3, l0, l1, l2, l3;
        split_bf(v0, h0, l0); split_bf(v1, h1, l1);
        split_bf(v2, h2, l2); split_bf(v3, h3, l3);
        *(uint32_t*)(sm + AH_OFF + r0 * ROWP + c * 2) = h0 | (h1 << 16);
        *(uint32_t*)(sm + AL_OFF + r0 * ROWP + c * 2) = l0 | (l1 << 16);
        *(uint32_t*)(sm + AH_OFF + r1 * ROWP + c * 2) = h2 | (h3 << 16);
        *(uint32_t*)(sm + AL_OFF + r1 * ROWP + c * 2) = l2 | (l3 << 16);
    }
}

// ================= fused node MLP (mma.sync) ================================
// writes h0 UNSCALED to hs (layer-0 aggregate applies rs_out at gather time)
__global__ __launch_bounds__(256) void mlp_mma_kernel(
        const float* __restrict__ x,
        const float* __restrict__ b1, const float* __restrict__ b2,
        const float* __restrict__ gam,
        float* __restrict__ hs, float* __restrict__ rep) {
    extern __shared__ char sm[];
    const uint32_t sb = smem_u32(sm);
    const int tid  = threadIdx.x;
    const int wid  = tid >> 5;
    const int lane = tid & 31;
    const int wm   = (wid & 3) * 16;
    const int wn   = (wid >> 2) * 64;
    const int blockRow = blockIdx.x * 64;

    // stage A = x rows (hi/lo split)
#pragma unroll
    for (int it = 0; it < 8; it++) {
        int idx4 = tid + it * 256;
        int r  = idx4 >> 5;
        int c4 = idx4 & 31;
        float4 v = make_float4(0.f, 0.f, 0.f, 0.f);
        if (blockRow + r < NN)
            v = *(const float4*)(x + (size_t)(blockRow + r) * D + c4 * 4);
        uint2 hi, lo;
        split4(v, hi, lo);
        *(uint2*)(sm + AH_OFF + r * ROWP + c4 * 8) = hi;
        *(uint2*)(sm + AL_OFF + r * ROWP + c4 * 8) = lo;
    }
    load_W(sm, 0, tid);
    __syncthreads();

    float acc[8][4];
    gemm_core(sb, acc, wm, wn, lane);
    __syncthreads();

    epi_to_A(sm, acc, b1, wm, wn, lane);
    load_W(sm, 1, tid);
    __syncthreads();

    gemm_core(sb, acc, wm, wn, lane);

    // epilogue 2: h = acc + b2 ; rep = g0*h ; hs = h (unscaled)
    {
        float g0 = gam[0];
        int r0 = blockRow + wm + (lane >> 2);
        int r1 = r0 + 8;
        bool ok0 = (r0 < NN), ok1 = (r1 < NN);
#pragma unroll
        for (int nt = 0; nt < 8; nt++) {
            int c = wn + nt * 8 + 2 * (lane & 3);
            float2 bv = *(const float2*)(b2 + c);
            if (ok0) {
                float h0 = acc[nt][0] + bv.x;
                float h1 = acc[nt][1] + bv.y;
                *(float2*)(rep + (size_t)r0 * D + c) = make_float2(g0 * h0, g0 * h1);
                *(float2*)(hs  + (size_t)r0 * D + c) = make_float2(h0, h1);
            }
            if (ok1) {
                float h2 = acc[nt][2] + bv.x;
                float h3 = acc[nt][3] + bv.y;
                *(float2*)(rep + (size_t)r1 * D + c) = make_float2(g0 * h2, g0 * h3);
                *(float2*)(hs  + (size_t)r1 * D + c) = make_float2(h2, h3);
            }
        }
    }
}

// ================= fused predictor (mma.sync) ===============================
__global__ __launch_bounds__(256) void pred_mma_kernel(
        const int* __restrict__ ps, const int* __restrict__ pd,
        const int* __restrict__ ns, const int* __restrict__ nd,
        const float* __restrict__ b1, const float* __restrict__ b2,
        const float* __restrict__ w3, const float* __restrict__ b3,
        const float* __restrict__ rep, float* __restrict__ out) {
    extern __shared__ char sm[];
    const uint32_t sb = smem_u32(sm);
    const int tid  = threadIdx.x;
    const int wid  = tid >> 5;
    const int lane = tid & 31;
    const int wm   = (wid & 3) * 16;
    const int wn   = (wid >> 2) * 64;
    const int base = blockIdx.x * 64;

    int* sidx = (int*)(sm + SIDX_OFF);
    int* didx = (int*)(sm + DIDX_OFF);
    float* part = (float*)(sm + PART_OFF);

    if (tid < 64) {
        int w = base + tid;
        int s, d;
        if (w < PP) { s = ps[w]; d = pd[w]; }
        else        { s = ns[w - PP]; d = nd[w - PP]; }
        sidx[tid] = s; didx[tid] = d;
    }
    __syncthreads();

    // stage E = rep[s]*rep[d] (hi/lo split)
#pragma unroll
    for (int it = 0; it < 8; it++) {
        int idx4 = tid + it * 256;
        int r  = idx4 >> 5;
        int c4 = idx4 & 31;
        float4 a = *(const float4*)(rep + (size_t)sidx[r] * D + c4 * 4);
        float4 b = *(const float4*)(rep + (size_t)didx[r] * D + c4 * 4);
        float4 v;
        v.x = a.x * b.x; v.y = a.y * b.y; v.z = a.z * b.z; v.w = a.w * b.w;
        uint2 hi, lo;
        split4(v, hi, lo);
        *(uint2*)(sm + AH_OFF + r * ROWP + c4 * 8) = hi;
        *(uint2*)(sm + AL_OFF + r * ROWP + c4 * 8) = lo;
    }
    load_W(sm, 2, tid);
    __syncthreads();

    float acc[8][4];
    gemm_core(sb, acc, wm, wn, lane);
    __syncthreads();

    epi_to_A(sm, acc, b1, wm, wn, lane);
    load_W(sm, 3, tid);
    __syncthreads();

    gemm_core(sb, acc, wm, wn, lane);

    // epilogue: p = sum_c relu(acc + b2[c]) * w3[c]
    {
        float p0 = 0.f, p1 = 0.f;
#pragma unroll
        for (int nt = 0; nt < 8; nt++) {
            int c = wn + nt * 8 + 2 * (lane & 3);
            float2 bv = *(const float2*)(b2 + c);
            float2 wv = *(const float2*)(w3 + c);
            p0 += fmaxf(acc[nt][0] + bv.x, 0.f) * wv.x
                + fmaxf(acc[nt][1] + bv.y, 0.f) * wv.y;
            p1 += fmaxf(acc[nt][2] + bv.x, 0.f) * wv.x
                + fmaxf(acc[nt][3] + bv.y, 0.f) * wv.y;
        }
        p0 += __shfl_xor_sync(0xFFFFFFFFu, p0, 1);
        p0 += __shfl_xor_sync(0xFFFFFFFFu, p0, 2);
        p1 += __shfl_xor_sync(0xFFFFFFFFu, p1, 1);
        p1 += __shfl_xor_sync(0xFFFFFFFFu, p1, 2);
        if ((lane & 3) == 0) {
            int g = (wn >> 6);
            int rl = wm + (lane >> 2);
            part[g * 64 + rl]     = p0;
            part[g * 64 + rl + 8] = p1;
        }
    }
    __syncthreads();
    if (tid < 64) {
        out[base + tid] = part[tid] + part[64 + tid] + b3[0];
    }
}

// ================= launch ===================================================
extern "C" void kernel_launch(void* const* d_in, const int* in_sizes, int n_in,
                              void* d_out, int out_size) {
    const float* x   = (const float*)d_in[0];
    const float* w1  = (const float*)d_in[1];
    const float* b1  = (const float*)d_in[2];
    const float* w2  = (const float*)d_in[3];
    const float* b2  = (const float*)d_in[4];
    const float* gam = (const float*)d_in[5];
    const float* pw1 = (const float*)d_in[6];
    const float* pb1 = (const float*)d_in[7];
    const float* pw2 = (const float*)d_in[8];
    const float* pb2 = (const float*)d_in[9];
    const float* pw3 = (const float*)d_in[10];
    const float* pb3 = (const float*)d_in[11];
    const int* src = (const int*)d_in[12];
    const int* dst = (const int*)d_in[13];
    const int* ps  = (const int*)d_in[14];
    const int* pd  = (const int*)d_in[15];
    const int* ns  = (const int*)d_in[16];
    const int* nd  = (const int*)d_in[17];
    float* out = (float*)d_out;

    void *vA, *vB, *vrep;
    cudaGetSymbolAddress(&vA,   g_hA);
    cudaGetSymbolAddress(&vB,   g_hB);
    cudaGetSymbolAddress(&vrep, g_rep);
    float* hA  = (float*)vA;
    float* hB  = (float*)vB;
    float* rep = (float*)vrep;

    cudaFuncSetAttribute(mlp_mma_kernel,  cudaFuncAttributeMaxDynamicSharedMemorySize, SMEM_TOT);
    cudaFuncSetAttribute(pred_mma_kernel, cudaFuncAttributeMaxDynamicSharedMemorySize, SMEM_TOT);

    // ---- fork: CSR setup on side stream, weights+MLP on origin stream ----
    cudaStream_t s1 = 0;
    cudaEvent_t eF = 0, eJ = 0;
    bool fork_ok =
        cudaStreamCreateWithFlags(&s1, cudaStreamNonBlocking) == cudaSuccess &&
        cudaEventCreateWithFlags(&eF, cudaEventDisableTiming) == cudaSuccess &&
        cudaEventCreateWithFlags(&eJ, cudaEventDisableTiming) == cudaSuccess;
    if (fork_ok)
        fork_ok = (cudaEventRecord(eF, 0) == cudaSuccess) &&
                  (cudaStreamWaitEvent(s1, eF, 0) == cudaSuccess);
    cudaStream_t ss = fork_ok ? s1 : (cudaStream_t)0;

    const int TB = 256;
    zero_cnt_kernel<<<NB, TB, 0, ss>>>();
    count_deg_kernel<<<(EE + TB - 1) / TB, TB, 0, ss>>>(src, dst);
    scanA_kernel<<<NB, TB, 0, ss>>>();
    scanB_kernel<<<1, 512, 0, ss>>>();
    scanC_kernel<<<NB, TB, 0, ss>>>();
    scatter_edges_kernel<<<(EE + TB - 1) / TB, TB, 0, ss>>>(src, dst);
    if (fork_ok) cudaEventRecord(eJ, s1);

    prep_w_kernel<<<4, 256>>>(w1, w2, pw1, pw2);
    mlp_mma_kernel<<<(NN + 63) / 64, TB, SMEM_TOT>>>(x, b1, b2, gam, hA, rep);

    if (fork_ok) cudaStreamWaitEvent((cudaStream_t)0, eJ, 0);

    aggregate_kernel<1, 0><<<(NN * 32 + TB - 1) / TB, TB>>>(hA, hB, gam, 0);
    aggregate_kernel<0, 0><<<(NN * 32 + TB - 1) / TB, TB>>>(hB, hA, gam, 1);
    aggregate_kernel<0, 1><<<(NN * 32 + TB - 1) / TB, TB>>>(hA, hB, gam, 2);

    pred_mma_kernel<<<(2 * PP) / 64, TB, SMEM_TOT>>>(
        ps, pd, ns, nd, pb1, pb2, pw3, pb3, rep, out);
}

// round 7
// speedup vs baseline: 2.2540x; 1.1134x over previous
#include <cuda_runtime.h>
#include <cuda_bf16.h>
#include <cuda_fp16.h>
#include <cstdint>

#define NN 100000
#define EE 1600000
#define PP 100000
#define D  128
#define NB 391   // ceil(NN/256)

// ---- smem layout (bytes) ----
#define ROWP     272            // 136 bf16 per row (128 used + pad)
#define AH_OFF   0              // A hi : 64 x ROWP
#define AL_OFF   17408
#define WH_OFF   34816          // W hi : 128 x ROWP
#define WL_OFF   69632          // contiguous after WH
#define SIDX_OFF 104448
#define DIDX_OFF 104704
#define PART_OFF 104960         // 2 x 64 floats
#define SMEM_TOT 105472

#define WTILE_B  34816          // 128 * ROWP

// ================= scratch (device globals; no allocation) =================
__device__ __align__(128) __half g_h0 [(size_t)NN * D];
__device__ __align__(128) __half g_h1 [(size_t)NN * D];
__device__ __align__(128) __half g_h2 [(size_t)NN * D];
__device__ __align__(128) float  g_rep[(size_t)NN * D];
__device__ __align__(16)  char   g_wt [4][2][WTILE_B];   // w1,w2,pw1,pw2 hi/lo
__device__ int   g_cnt_in [NN];
__device__ int   g_cnt_out[NN];
__device__ float g_rs_in  [NN];
__device__ float g_rs_out [NN];
__device__ int   g_row_ptr[NN + 1];
__device__ int   g_cursor [NN];
__device__ int   g_col    [EE];
__device__ int   g_bsum   [NB];
__device__ int   g_boff   [NB];

// ================= graph structure (unchanged, measured-good) ==============
__global__ void zero_cnt_kernel() {
    int v = blockIdx.x * blockDim.x + threadIdx.x;
    if (v < NN) { g_cnt_in[v] = 0; g_cnt_out[v] = 0; }
}

__global__ void count_deg_kernel(const int* __restrict__ src, const int* __restrict__ dst) {
    int e = blockIdx.x * blockDim.x + threadIdx.x;
    if (e < EE) {
        atomicAdd(&g_cnt_out[src[e]], 1);
        atomicAdd(&g_cnt_in [dst[e]], 1);
    }
}

__global__ void scanA_kernel() {
    __shared__ int sh[256];
    int i = blockIdx.x * 256 + threadIdx.x;
    int v = (i < NN) ? g_cnt_in[i] : 0;
    sh[threadIdx.x] = v;
    __syncthreads();
    for (int off = 128; off > 0; off >>= 1) {
        if (threadIdx.x < off) sh[threadIdx.x] += sh[threadIdx.x + off];
        __syncthreads();
    }
    if (threadIdx.x == 0) g_bsum[blockIdx.x] = sh[0];
}

__global__ void scanB_kernel() {
    __shared__ int sh[512];
    int t = threadIdx.x;
    int v = (t < NB) ? g_bsum[t] : 0;
    sh[t] = v;
    __syncthreads();
    for (int off = 1; off < 512; off <<= 1) {
        int x = (t >= off) ? sh[t - off] : 0;
        __syncthreads();
        sh[t] += x;
        __syncthreads();
    }
    if (t < NB) g_boff[t] = sh[t] - v;
}

__global__ void scanC_kernel() {
    __shared__ int sh[256];
    int b = blockIdx.x;
    int i = b * 256 + threadIdx.x;
    int v = (i < NN) ? g_cnt_in[i] : 0;
    sh[threadIdx.x] = v;
    __syncthreads();
    for (int off = 1; off < 256; off <<= 1) {
        int x = (threadIdx.x >= off) ? sh[threadIdx.x - off] : 0;
        __syncthreads();
        sh[threadIdx.x] += x;
        __syncthreads();
    }
    if (i < NN) {
        int incl = g_boff[b] + sh[threadIdx.x];
        g_row_ptr[i + 1] = incl;
        g_cursor[i] = incl - v;
        int ci = v; if (ci < 1) ci = 1;
        int co = g_cnt_out[i]; if (co < 1) co = 1;
        g_rs_in [i] = rsqrtf((float)ci);
        g_rs_out[i] = rsqrtf((float)co);
        if (i == 0) g_row_ptr[0] = 0;
    }
}

__global__ void scatter_edges_kernel(const int* __restrict__ src, const int* __restrict__ dst) {
    int e = blockIdx.x * blockDim.x + threadIdx.x;
    if (e < EE) {
        int pos = atomicAdd(&g_cursor[dst[e]], 1);
        g_col[pos] = src[e];
    }
}

// ================= bf16 split helpers =======================================
__device__ __forceinline__ void split_bf(float v, unsigned& h, unsigned& l) {
    __nv_bfloat16 hb = __float2bfloat16(v);
    float r = v - __bfloat162float(hb);
    __nv_bfloat16 lb = __float2bfloat16(r);
    h = (unsigned)__bfloat16_as_ushort(hb);
    l = (unsigned)__bfloat16_as_ushort(lb);
}
__device__ __forceinline__ void split4(float4 v, uint2& hi, uint2& lo) {
    unsigned h0, h1, h2, h3, l0, l1, l2, l3;
    split_bf(v.x, h0, l0);
    split_bf(v.y, h1, l1);
    split_bf(v.z, h2, l2);
    split_bf(v.w, h3, l3);
    hi.x = h0 | (h1 << 16); hi.y = h2 | (h3 << 16);
    lo.x = l0 | (l1 << 16); lo.y = l2 | (l3 << 16);
}

// precompute padded bf16 hi/lo weight tiles (one block per weight matrix)
__global__ void prep_w_kernel(const float* __restrict__ w1, const float* __restrict__ w2,
                              const float* __restrict__ pw1, const float* __restrict__ pw2) {
    const float* W = (blockIdx.x == 0) ? w1 : (blockIdx.x == 1) ? w2
                   : (blockIdx.x == 2) ? pw1 : pw2;
    char* hiB = &g_wt[blockIdx.x][0][0];
    char* loB = &g_wt[blockIdx.x][1][0];
    int tid = threadIdx.x;
#pragma unroll
    for (int it = 0; it < 16; it++) {
        int idx4 = tid + it * 256;      // 0..4095
        int k  = idx4 >> 5;
        int c4 = idx4 & 31;
        float4 v = *(const float4*)(W + (size_t)k * 128 + c4 * 4);
        uint2 hi, lo;
        split4(v, hi, lo);
        *(uint2*)(hiB + k * ROWP + c4 * 8) = hi;
        *(uint2*)(loB + k * ROWP + c4 * 8) = lo;
    }
}

// ================= graph conv (fp16 features) ===============================
__device__ __forceinline__ void acc_edge(float4& acc, const __half* __restrict__ hin,
                                         int s, int lane) {
    float m = g_rs_out[s];
    uint2 rv = *(const uint2*)(hin + (size_t)s * D + lane * 4);
    __half2 p0 = *reinterpret_cast<__half2*>(&rv.x);
    __half2 p1 = *reinterpret_cast<__half2*>(&rv.y);
    float2 f0 = __half22float2(p0);
    float2 f1 = __half22float2(p1);
    acc.x = fmaf(m, f0.x, acc.x);
    acc.y = fmaf(m, f0.y, acc.y);
    acc.z = fmaf(m, f1.x, acc.z);
    acc.w = fmaf(m, f1.y, acc.w);
}

__device__ __forceinline__ float4 gather_row(const __half* __restrict__ hin,
                                             int w, int lane) {
    int beg = g_row_ptr[w];
    int end = g_row_ptr[w + 1];
    float4 acc = make_float4(0.f, 0.f, 0.f, 0.f);
    int e = beg;
    for (; e + 4 <= end; e += 4) {
        int s0 = g_col[e], s1 = g_col[e + 1], s2 = g_col[e + 2], s3 = g_col[e + 3];
        acc_edge(acc, hin, s0, lane);
        acc_edge(acc, hin, s1, lane);
        acc_edge(acc, hin, s2, lane);
        acc_edge(acc, hin, s3, lane);
    }
    for (; e < end; e++) acc_edge(acc, hin, g_col[e], lane);
    return acc;
}

// mid layer: hout = fp16( rs_in[w] * sum_e rs_out[src]*hin[src] )
__global__ void aggregate_mid_kernel(const __half* __restrict__ hin,
                                     __half* __restrict__ hout) {
    int w    = (blockIdx.x * blockDim.x + threadIdx.x) >> 5;
    int lane = threadIdx.x & 31;
    if (w >= NN) return;
    float4 acc = gather_row(hin, w, lane);
    float rin = g_rs_in[w];
    __half2 o0 = __floats2half2_rn(rin * acc.x, rin * acc.y);
    __half2 o1 = __floats2half2_rn(rin * acc.z, rin * acc.w);
    uint2 ov;
    ov.x = *reinterpret_cast<uint32_t*>(&o0);
    ov.y = *reinterpret_cast<uint32_t*>(&o1);
    *(uint2*)(hout + (size_t)w * D + lane * 4) = ov;
}

// last layer: rep += g1*h1_16 + g2*h2_16 + g3*(rs_in*sum)
__global__ void aggregate_last_kernel(const __half* __restrict__ hin,   // h2_16
                                      const __half* __restrict__ h1_16,
                                      const float* __restrict__ gamma) {
    int w    = (blockIdx.x * blockDim.x + threadIdx.x) >> 5;
    int lane = threadIdx.x & 31;
    if (w >= NN) return;
    float4 acc = gather_row(hin, w, lane);
    float rin = g_rs_in[w];
    float g1 = gamma[1], g2 = gamma[2], g3 = gamma[3];
    size_t off = (size_t)w * D + lane * 4;

    uint2 r1 = *(const uint2*)(h1_16 + off);
    uint2 r2 = *(const uint2*)(hin + off);
    float2 a1 = __half22float2(*reinterpret_cast<__half2*>(&r1.x));
    float2 b1v = __half22float2(*reinterpret_cast<__half2*>(&r1.y));
    float2 a2 = __half22float2(*reinterpret_cast<__half2*>(&r2.x));
    float2 b2v = __half22float2(*reinterpret_cast<__half2*>(&r2.y));

    float4 rp = *(const float4*)&g_rep[off];
    rp.x += g1 * a1.x + g2 * a2.x + g3 * rin * acc.x;
    rp.y += g1 * a1.y + g2 * a2.y + g3 * rin * acc.y;
    rp.z += g1 * b1v.x + g2 * b2v.x + g3 * rin * acc.z;
    rp.w += g1 * b1v.y + g2 * b2v.y + g3 * rin * acc.w;
    *(float4*)&g_rep[off] = rp;
}

// ================= mma.sync plumbing (virtual-arch-safe PTX) ================
__device__ __forceinline__ uint32_t smem_u32(const void* p) {
    uint32_t a;
    asm("{ .reg .u64 t; cvta.to.shared.u64 t, %1; cvt.u32.u64 %0, t; }" : "=r"(a) : "l"(p));
    return a;
}

#define LDSM_X4(R, A)                                                        \
    asm volatile("ldmatrix.sync.aligned.m8n8.x4.shared.b16 {%0,%1,%2,%3}, [%4];" \
        : "=r"((R)[0]), "=r"((R)[1]), "=r"((R)[2]), "=r"((R)[3]) : "r"(A))

#define LDSM_X4T(R, A)                                                       \
    asm volatile("ldmatrix.sync.aligned.m8n8.x4.trans.shared.b16 {%0,%1,%2,%3}, [%4];" \
        : "=r"((R)[0]), "=r"((R)[1]), "=r"((R)[2]), "=r"((R)[3]) : "r"(A))

#define MMA16816(C, AR, B0, B1)                                              \
    asm volatile("mma.sync.aligned.m16n8k16.row.col.f32.bf16.bf16.f32 "      \
        "{%0,%1,%2,%3}, {%4,%5,%6,%7}, {%8,%9}, {%0,%1,%2,%3};"              \
        : "+f"((C)[0]), "+f"((C)[1]), "+f"((C)[2]), "+f"((C)[3])             \
        : "r"((AR)[0]), "r"((AR)[1]), "r"((AR)[2]), "r"((AR)[3]),            \
          "r"(B0), "r"(B1))

// copy precomputed hi+lo weight tile (69632 B contiguous) into smem
__device__ __forceinline__ void load_W(char* sm, int widx, int tid) {
    const uint4* src = (const uint4*)&g_wt[widx][0][0];
    uint4* dst = (uint4*)(sm + WH_OFF);
#pragma unroll
    for (int i = 0; i < 17; i++)
        dst[tid + i * 256] = src[tid + i * 256];
}

// 64x128 GEMM core: warp tile 16x64; 3-pass bf16 split
__device__ __forceinline__ void gemm_core(uint32_t sb, float acc[8][4],
                                          int wm, int wn, int lane) {
#pragma unroll
    for (int i = 0; i < 8; i++)
#pragma unroll
        for (int j = 0; j < 4; j++) acc[i][j] = 0.f;

    const uint32_t a_addr = sb + AH_OFF + (uint32_t)(wm + (lane & 15)) * ROWP
                            + ((lane >> 4) << 4);
    const uint32_t b_row  = (uint32_t)(lane & 15) * ROWP;
    const uint32_t b_col  = (uint32_t)wn * 2 + ((lane >> 4) << 4);

#pragma unroll
    for (int ks = 0; ks < 8; ks++) {
        uint32_t ah[4], al[4];
        LDSM_X4(ah, a_addr + ks * 32);
        LDSM_X4(al, a_addr + ks * 32 + (AL_OFF - AH_OFF));
        uint32_t bbase = sb + WH_OFF + (uint32_t)(ks * 16) * ROWP + b_row + b_col;
#pragma unroll
        for (int g = 0; g < 4; g++) {
            uint32_t bh[4], bl[4];
            uint32_t ba = bbase + g * 32;
            LDSM_X4T(bh, ba);
            LDSM_X4T(bl, ba + (WL_OFF - WH_OFF));
            MMA16816(acc[2 * g],     ah, bh[0], bh[1]);
            MMA16816(acc[2 * g + 1], ah, bh[2], bh[3]);
            MMA16816(acc[2 * g],     ah, bl[0], bl[1]);
            MMA16816(acc[2 * g + 1], ah, bl[2], bl[3]);
            MMA16816(acc[2 * g],     al, bh[0], bh[1]);
            MMA16816(acc[2 * g + 1], al, bh[2], bh[3]);
        }
    }
}

// relu(acc + bias) -> back into A smem tiles (bf16 hi/lo)
__device__ __forceinline__ void epi_to_A(char* sm, float acc[8][4],
                                         const float* __restrict__ bias,
                                         int wm, int wn, int lane) {
    int r0 = wm + (lane >> 2);
    int r1 = r0 + 8;
#pragma unroll
    for (int nt = 0; nt < 8; nt++) {
        int c = wn + nt * 8 + 2 * (lane & 3);
        float2 bv = *(const float2*)(bias + c);
        float v0 = fmaxf(acc[nt][0] + bv.x, 0.f);
        float v1 = fmaxf(acc[nt][1] + bv.y, 0.f);
        float v2 = fmaxf(acc[nt][2] + bv.x, 0.f);
        float v3 = fmaxf(acc[nt][3] + bv.y, 0.f);
        unsigned h0, h1, h2, h3, l0, l1, l2, l3;
        split_bf(v0, h0, l0); split_bf(v1, h1, l1);
        split_bf(v2, h2, l2); split_bf(v3, h3, l3);
        *(uint32_t*)(sm + AH_OFF + r0 * ROWP + c * 2) = h0 | (h1 << 16);
        *(uint32_t*)(sm + AL_OFF + r0 * ROWP + c * 2) = l0 | (l1 << 16);
        *(uint32_t*)(sm + AH_OFF + r1 * ROWP + c * 2) = h2 | (h3 << 16);
        *(uint32_t*)(sm + AL_OFF + r1 * ROWP + c * 2) = l2 | (l3 << 16);
    }
}

// ================= fused node MLP (mma.sync) ================================
// writes h0 (unscaled, fp16) + rep = gamma0*h0 (fp32)
__global__ __launch_bounds__(256) void mlp_mma_kernel(
        const float* __restrict__ x,
        const float* __restrict__ b1, const float* __restrict__ b2,
        const float* __restrict__ gam,
        __half* __restrict__ hs16, float* __restrict__ rep) {
    extern __shared__ char sm[];
    const uint32_t sb = smem_u32(sm);
    const int tid  = threadIdx.x;
    const int wid  = tid >> 5;
    const int lane = tid & 31;
    const int wm   = (wid & 3) * 16;
    const int wn   = (wid >> 2) * 64;
    const int blockRow = blockIdx.x * 64;

    // stage A = x rows (hi/lo split)
#pragma unroll
    for (int it = 0; it < 8; it++) {
        int idx4 = tid + it * 256;
        int r  = idx4 >> 5;
        int c4 = idx4 & 31;
        float4 v = make_float4(0.f, 0.f, 0.f, 0.f);
        if (blockRow + r < NN)
            v = *(const float4*)(x + (size_t)(blockRow + r) * D + c4 * 4);
        uint2 hi, lo;
        split4(v, hi, lo);
        *(uint2*)(sm + AH_OFF + r * ROWP + c4 * 8) = hi;
        *(uint2*)(sm + AL_OFF + r * ROWP + c4 * 8) = lo;
    }
    load_W(sm, 0, tid);
    __syncthreads();

    float acc[8][4];
    gemm_core(sb, acc, wm, wn, lane);
    __syncthreads();

    epi_to_A(sm, acc, b1, wm, wn, lane);
    load_W(sm, 1, tid);
    __syncthreads();

    gemm_core(sb, acc, wm, wn, lane);

    // epilogue 2: h = acc + b2 ; rep = g0*h ; hs16 = fp16(h)
    {
        float g0 = gam[0];
        int r0 = blockRow + wm + (lane >> 2);
        int r1 = r0 + 8;
        bool ok0 = (r0 < NN), ok1 = (r1 < NN);
#pragma unroll
        for (int nt = 0; nt < 8; nt++) {
            int c = wn + nt * 8 + 2 * (lane & 3);
            float2 bv = *(const float2*)(b2 + c);
            if (ok0) {
                float h0 = acc[nt][0] + bv.x;
                float h1 = acc[nt][1] + bv.y;
                *(float2*)(rep + (size_t)r0 * D + c) = make_float2(g0 * h0, g0 * h1);
                __half2 hh = __floats2half2_rn(h0, h1);
                *(uint32_t*)(hs16 + (size_t)r0 * D + c) = *reinterpret_cast<uint32_t*>(&hh);
            }
            if (ok1) {
                float h2 = acc[nt][2] + bv.x;
                float h3 = acc[nt][3] + bv.y;
                *(float2*)(rep + (size_t)r1 * D + c) = make_float2(g0 * h2, g0 * h3);
                __half2 hh = __floats2half2_rn(h2, h3);
                *(uint32_t*)(hs16 + (size_t)r1 * D + c) = *reinterpret_cast<uint32_t*>(&hh);
            }
        }
    }
}

// ================= fused predictor (mma.sync) ===============================
__global__ __launch_bounds__(256) void pred_mma_kernel(
        const int* __restrict__ ps, const int* __restrict__ pd,
        const int* __restrict__ ns, const int* __restrict__ nd,
        const float* __restrict__ b1, const float* __restrict__ b2,
        const float* __restrict__ w3, const float* __restrict__ b3,
        const float* __restrict__ rep, float* __restrict__ out) {
    extern __shared__ char sm[];
    const uint32_t sb = smem_u32(sm);
    const int tid  = threadIdx.x;
    const int wid  = tid >> 5;
    const int lane = tid & 31;
    const int wm   = (wid & 3) * 16;
    const int wn   = (wid >> 2) * 64;
    const int base = blockIdx.x * 64;

    int* sidx = (int*)(sm + SIDX_OFF);
    int* didx = (int*)(sm + DIDX_OFF);
    float* part = (float*)(sm + PART_OFF);

    if (tid < 64) {
        int w = base + tid;
        int s, d;
        if (w < PP) { s = ps[w]; d = pd[w]; }
        else        { s = ns[w - PP]; d = nd[w - PP]; }
        sidx[tid] = s; didx[tid] = d;
    }
    __syncthreads();

    // stage E = rep[s]*rep[d] (hi/lo split)
#pragma unroll
    for (int it = 0; it < 8; it++) {
        int idx4 = tid + it * 256;
        int r  = idx4 >> 5;
        int c4 = idx4 & 31;
        float4 a = *(const float4*)(rep + (size_t)sidx[r] * D + c4 * 4);
        float4 b = *(const float4*)(rep + (size_t)didx[r] * D + c4 * 4);
        float4 v;
        v.x = a.x * b.x; v.y = a.y * b.y; v.z = a.z * b.z; v.w = a.w * b.w;
        uint2 hi, lo;
        split4(v, hi, lo);
        *(uint2*)(sm + AH_OFF + r * ROWP + c4 * 8) = hi;
        *(uint2*)(sm + AL_OFF + r * ROWP + c4 * 8) = lo;
    }
    load_W(sm, 2, tid);
    __syncthreads();

    float acc[8][4];
    gemm_core(sb, acc, wm, wn, lane);
    __syncthreads();

    epi_to_A(sm, acc, b1, wm, wn, lane);
    load_W(sm, 3, tid);
    __syncthreads();

    gemm_core(sb, acc, wm, wn, lane);

    // epilogue: p = sum_c relu(acc + b2[c]) * w3[c]
    {
        float p0 = 0.f, p1 = 0.f;
#pragma unroll
        for (int nt = 0; nt < 8; nt++) {
            int c = wn + nt * 8 + 2 * (lane & 3);
            float2 bv = *(const float2*)(b2 + c);
            float2 wv = *(const float2*)(w3 + c);
            p0 += fmaxf(acc[nt][0] + bv.x, 0.f) * wv.x
                + fmaxf(acc[nt][1] + bv.y, 0.f) * wv.y;
            p1 += fmaxf(acc[nt][2] + bv.x, 0.f) * wv.x
                + fmaxf(acc[nt][3] + bv.y, 0.f) * wv.y;
        }
        p0 += __shfl_xor_sync(0xFFFFFFFFu, p0, 1);
        p0 += __shfl_xor_sync(0xFFFFFFFFu, p0, 2);
        p1 += __shfl_xor_sync(0xFFFFFFFFu, p1, 1);
        p1 += __shfl_xor_sync(0xFFFFFFFFu, p1, 2);
        if ((lane & 3) == 0) {
            int g = (wn >> 6);
            int rl = wm + (lane >> 2);
            part[g * 64 + rl]     = p0;
            part[g * 64 + rl + 8] = p1;
        }
    }
    __syncthreads();
    if (tid < 64) {
        out[base + tid] = part[tid] + part[64 + tid] + b3[0];
    }
}

// ================= launch ===================================================
extern "C" void kernel_launch(void* const* d_in, const int* in_sizes, int n_in,
                              void* d_out, int out_size) {
    const float* x   = (const float*)d_in[0];
    const float* w1  = (const float*)d_in[1];
    const float* b1  = (const float*)d_in[2];
    const float* w2  = (const float*)d_in[3];
    const float* b2  = (const float*)d_in[4];
    const float* gam = (const float*)d_in[5];
    const float* pw1 = (const float*)d_in[6];
    const float* pb1 = (const float*)d_in[7];
    const float* pw2 = (const float*)d_in[8];
    const float* pb2 = (const float*)d_in[9];
    const float* pw3 = (const float*)d_in[10];
    const float* pb3 = (const float*)d_in[11];
    const int* src = (const int*)d_in[12];
    const int* dst = (const int*)d_in[13];
    const int* ps  = (const int*)d_in[14];
    const int* pd  = (const int*)d_in[15];
    const int* ns  = (const int*)d_in[16];
    const int* nd  = (const int*)d_in[17];
    float* out = (float*)d_out;

    void *v0, *v1, *v2, *vrep;
    cudaGetSymbolAddress(&v0,   g_h0);
    cudaGetSymbolAddress(&v1,   g_h1);
    cudaGetSymbolAddress(&v2,   g_h2);
    cudaGetSymbolAddress(&vrep, g_rep);
    __half* h0 = (__half*)v0;
    __half* h1 = (__half*)v1;
    __half* h2 = (__half*)v2;
    float* rep = (float*)vrep;

    cudaFuncSetAttribute(mlp_mma_kernel,  cudaFuncAttributeMaxDynamicSharedMemorySize, SMEM_TOT);
    cudaFuncSetAttribute(pred_mma_kernel, cudaFuncAttributeMaxDynamicSharedMemorySize, SMEM_TOT);

    // ---- fork: CSR setup on side stream, weights+MLP on origin stream ----
    cudaStream_t s1 = 0;
    cudaEvent_t eF = 0, eJ = 0;
    bool fork_ok =
        cudaStreamCreateWithFlags(&s1, cudaStreamNonBlocking) == cudaSuccess &&
        cudaEventCreateWithFlags(&eF, cudaEventDisableTiming) == cudaSuccess &&
        cudaEventCreateWithFlags(&eJ, cudaEventDisableTiming) == cudaSuccess;
    if (fork_ok)
        fork_ok = (cudaEventRecord(eF, 0) == cudaSuccess) &&
                  (cudaStreamWaitEvent(s1, eF, 0) == cudaSuccess);
    cudaStream_t ss = fork_ok ? s1 : (cudaStream_t)0;

    const int TB = 256;
    zero_cnt_kernel<<<NB, TB, 0, ss>>>();
    count_deg_kernel<<<(EE + TB - 1) / TB, TB, 0, ss>>>(src, dst);
    scanA_kernel<<<NB, TB, 0, ss>>>();
    scanB_kernel<<<1, 512, 0, ss>>>();
    scanC_kernel<<<NB, TB, 0, ss>>>();
    scatter_edges_kernel<<<(EE + TB - 1) / TB, TB, 0, ss>>>(src, dst);
    if (fork_ok) cudaEventRecord(eJ, s1);

    prep_w_kernel<<<4, 256>>>(w1, w2, pw1, pw2);
    mlp_mma_kernel<<<(NN + 63) / 64, TB, SMEM_TOT>>>(x, b1, b2, gam, h0, rep);

    if (fork_ok) cudaStreamWaitEvent((cudaStream_t)0, eJ, 0);

    aggregate_mid_kernel <<<(NN * 32 + TB - 1) / TB, TB>>>(h0, h1);
    aggregate_mid_kernel <<<(NN * 32 + TB - 1) / TB, TB>>>(h1, h2);
    aggregate_last_kernel<<<(NN * 32 + TB - 1) / TB, TB>>>(h2, h1, gam);

    pred_mma_kernel<<<(2 * PP) / 64, TB, SMEM_TOT>>>(
        ps, pd, ns, nd, pb1, pb2, pw3, pb3, rep, out);
}